// round 1
// baseline (speedup 1.0000x reference)
#include <cuda_runtime.h>
#include <cstddef>

typedef unsigned long long u64;

#define RHO 5
#define NJ 5
#define NN 4096
#define DD 128
#define NB 2

// ---- device scratch (allocation-free rule: __device__ globals) ----
__device__ float g_partial[NB * 32 * DD];
__device__ float g_acoef[NB * 8];
__device__ float g_bcoef[NB * 8];
__device__ float g_scale[NB * 8];
__device__ float g_Wcat[6 * DD * DD];     // [768][128] combined (WS@Ww, WM[j]@Ww)
__device__ float g_cvec[DD];              // combined bias
__device__ float g_xt[NB * NN * DD];      // U^T x
__device__ float g_F[(size_t)NB * NN * 6 * DD]; // filter-bank features [8192][768]
__device__ float g_Z[NB * NN * DD];       // F @ Wcat

// ---------------------------------------------------------------
// Stage 1: partial column sums of eigvs (for the pooled means)
// grid 64 (b*32+chunk), 128 threads
// ---------------------------------------------------------------
__global__ void partial_kernel(const float* __restrict__ eigvs) {
    int b = blockIdx.x >> 5, chunk = blockIdx.x & 31, d = threadIdx.x;
    const float* p = eigvs + ((size_t)b * NN + (size_t)chunk * 128) * DD + d;
    float s = 0.f;
#pragma unroll 8
    for (int r = 0; r < 128; r++) s += p[(size_t)r * DD];
    g_partial[(b * 32 + chunk) * DD + d] = s;
}

// ---------------------------------------------------------------
// Stage 2: reduce means -> Chebyshev coefficients a,b and scales
// grid 2 (batch), 128 threads
// ---------------------------------------------------------------
__global__ void coeff_kernel(const float* __restrict__ Wa, const float* __restrict__ ba,
                             const float* __restrict__ Wb, const float* __restrict__ bb,
                             const float* __restrict__ Ws, const float* __restrict__ bs) {
    __shared__ float mean[DD];
    int b = blockIdx.x, d = threadIdx.x;
    float s = 0.f;
    for (int c = 0; c < 32; c++) s += g_partial[(b * 32 + c) * DD + d];
    mean[d] = s * (1.0f / NN);
    __syncthreads();
    if (d < RHO) {
        float a = 0.f, bv = 0.f, sv = 0.f;
        for (int e = 0; e < DD; e++) {
            float m = mean[e];
            a += m * Wa[e * RHO + d];
            bv += m * Wb[e * RHO + d];
            sv += m * Ws[e * NJ + d];
        }
        g_acoef[b * 8 + d] = a + ba[d];
        g_bcoef[b * 8 + d] = bv + bb[d];
        sv += bs[d];
        g_scale[b * 8 + d] = 5.0f / (1.0f + expf(-sv));  // sigmoid * SCALE
    }
}

// ---------------------------------------------------------------
// Stage 3: fold channel matrices through Ww:
//   Wcat[s*128+i][d] = sum_e Wsrc_s[i][e] * Ww[e][d]
//   cvec[d] = (bS + sum_j bM[j]) @ Ww + bw
// grid 769, 128 threads
// ---------------------------------------------------------------
__global__ void weight_kernel(const float* __restrict__ WS_, const float* __restrict__ WM,
                              const float* __restrict__ Ww, const float* __restrict__ bS,
                              const float* __restrict__ bM, const float* __restrict__ bw) {
    int blk = blockIdx.x, d = threadIdx.x;
    if (blk < 6 * DD) {
        int s = blk >> 7, i = blk & 127;
        const float* wsrc = (s == 0) ? (WS_ + i * DD) : (WM + (size_t)(s - 1) * DD * DD + i * DD);
        float acc = 0.f;
        for (int e = 0; e < DD; e++) acc += wsrc[e] * Ww[e * DD + d];
        g_Wcat[blk * DD + d] = acc;
    } else {
        float acc = bw[d];
        for (int e = 0; e < DD; e++) {
            float cb = bS[e];
            for (int j = 0; j < NJ; j++) cb += bM[j * DD + e];
            acc += cb * Ww[e * DD + d];
        }
        g_cvec[d] = acc;
    }
}

// ---------------------------------------------------------------
// Stage 5: build filter-bank features
//   F[row][0*128+d]    = h(e) * xt
//   F[row][(1+j)*128+d]= g_j(scale_j*e) * xt
// grid 512 (16 rows each), 128 threads
// ---------------------------------------------------------------
__global__ void fbuild_kernel(const float* __restrict__ eigvs) {
    int row0 = blockIdx.x * 16;
    int d = threadIdx.x;
    for (int r = 0; r < 16; r++) {
        int row = row0 + r;
        int b = row >> 12;
        const float* ac = g_acoef + b * 8;
        const float* bc = g_bcoef + b * 8;
        const float* sc = g_scale + b * 8;
        float e = eigvs[(size_t)row * DD + d];
        float xv = g_xt[(size_t)row * DD + d];
        // h = sum_i b_i T_{2i}(e)  (reference recurrence exactly)
        float To = 1.f, Te = e, h = bc[0];
#pragma unroll
        for (int i = 1; i < RHO; i++) {
            To = 2.f * e * Te - To;
            Te = 2.f * e * To - Te;
            h += bc[i] * To;
        }
        float* Fr = g_F + (size_t)row * (6 * DD);
        Fr[d] = h * xv;
#pragma unroll
        for (int j = 0; j < NJ; j++) {
            float sx = sc[j] * e;
            float To2 = 1.f, Te2 = sx, g = ac[0] * Te2;
#pragma unroll
            for (int i = 1; i < RHO; i++) {
                To2 = 2.f * sx * Te2 - To2;
                Te2 = 2.f * sx * To2 - Te2;
                g += ac[i] * Te2;
            }
            Fr[(1 + j) * DD + d] = g * xv;
        }
    }
}

// ---------------------------------------------------------------
// GEMM: C[M,128] = op(A) @ B[K,128] (+bias).  BM=64, BN=128, BK=32.
// 256 threads, each thread: 4 rows x 8 cols as 4x4 f32x2 accumulators.
// Register-prefetched single smem buffer. Uses packed fma.rn.f32x2
// (FFMA2) for 2x fp32 FMA throughput on sm_103a.
// TRANS_A: A element (k, row) at A[k*lda + row]   (U^T x case)
// else:    A element (row, k) at A[row*lda + k]
// ---------------------------------------------------------------
template <bool TRANS_A, bool ADD_BIAS>
__global__ void __launch_bounds__(256)
gemm_n128(const float* __restrict__ A, const float* __restrict__ B,
          float* __restrict__ C, const float* __restrict__ bias,
          int K, int lda, size_t strideA, size_t strideB, size_t strideC) {
    __shared__ float As[32][65];
    __shared__ __align__(16) float Bs[32][128];

    const int tid = threadIdx.x;
    const int m0 = blockIdx.x * 64;
    const int bb = blockIdx.y;
    A += (size_t)bb * strideA;
    B += (size_t)bb * strideB;
    C += (size_t)bb * strideC;

    const int rbase = (tid >> 4) << 2;  // 0..60
    const int cbase = (tid & 15) << 3;  // 0..120

    u64 acc[4][4];
#pragma unroll
    for (int i = 0; i < 4; i++)
#pragma unroll
        for (int j = 0; j < 4; j++) acc[i][j] = 0ULL;

    // per-thread load coordinates
    const int kk0A = TRANS_A ? (tid >> 6) : (tid & 31);
    const int mmA = TRANS_A ? (tid & 63) : (tid >> 5);
    const int kkB = tid >> 5;
    const int c4 = (tid & 31) * 4;

    float aR[8];
    float4 bR[4];
    // prologue: load tile k0=0 into registers
#pragma unroll
    for (int i = 0; i < 8; i++) {
        if (TRANS_A)
            aR[i] = A[(size_t)(kk0A + 4 * i) * lda + m0 + mmA];
        else
            aR[i] = A[(size_t)(m0 + mmA + 8 * i) * lda + kk0A];
    }
#pragma unroll
    for (int i = 0; i < 4; i++)
        bR[i] = *(const float4*)&B[(size_t)(kkB + 8 * i) * 128 + c4];

    for (int k0 = 0; k0 < K; k0 += 32) {
        // stage registers -> smem
#pragma unroll
        for (int i = 0; i < 8; i++) {
            if (TRANS_A)
                As[kk0A + 4 * i][mmA] = aR[i];
            else
                As[kk0A][mmA + 8 * i] = aR[i];
        }
#pragma unroll
        for (int i = 0; i < 4; i++)
            *(float4*)&Bs[kkB + 8 * i][c4] = bR[i];
        __syncthreads();

        // prefetch next tile to registers (in flight during compute)
        const int kn = k0 + 32;
        if (kn < K) {
#pragma unroll
            for (int i = 0; i < 8; i++) {
                if (TRANS_A)
                    aR[i] = A[(size_t)(kn + kk0A + 4 * i) * lda + m0 + mmA];
                else
                    aR[i] = A[(size_t)(m0 + mmA + 8 * i) * lda + kn + kk0A];
            }
#pragma unroll
            for (int i = 0; i < 4; i++)
                bR[i] = *(const float4*)&B[(size_t)(kn + kkB + 8 * i) * 128 + c4];
        }

        // compute 32 k-steps with packed f32x2 FMAs
#pragma unroll
        for (int kk = 0; kk < 32; kk++) {
            u64 ap[4];
#pragma unroll
            for (int i = 0; i < 4; i++) {
                float av = As[kk][rbase + i];
                asm("mov.b64 %0, {%1, %1};" : "=l"(ap[i]) : "f"(av));
            }
            const ulonglong2* bq = (const ulonglong2*)&Bs[kk][cbase];
            ulonglong2 q0 = bq[0], q1 = bq[1];
            u64 bp[4] = {q0.x, q0.y, q1.x, q1.y};
#pragma unroll
            for (int i = 0; i < 4; i++)
#pragma unroll
                for (int j = 0; j < 4; j++)
                    asm("fma.rn.f32x2 %0, %1, %2, %0;"
                        : "+l"(acc[i][j])
                        : "l"(ap[i]), "l"(bp[j]));
        }
        __syncthreads();
    }

    // epilogue
#pragma unroll
    for (int i = 0; i < 4; i++) {
        float out[8];
#pragma unroll
        for (int j = 0; j < 4; j++) {
            float lo, hi;
            asm("mov.b64 {%0, %1}, %2;" : "=f"(lo), "=f"(hi) : "l"(acc[i][j]));
            out[2 * j] = lo;
            out[2 * j + 1] = hi;
        }
        if (ADD_BIAS) {
#pragma unroll
            for (int j = 0; j < 8; j++) out[j] += bias[cbase + j];
        }
        float4* dst = (float4*)&C[(size_t)(m0 + rbase + i) * 128 + cbase];
        dst[0] = make_float4(out[0], out[1], out[2], out[3]);
        dst[1] = make_float4(out[4], out[5], out[6], out[7]);
    }
}

// ---------------------------------------------------------------
extern "C" void kernel_launch(void* const* d_in, const int* in_sizes, int n_in,
                              void* d_out, int out_size) {
    const float* eigvs = (const float*)d_in[0];
    const float* x = (const float*)d_in[1];
    const float* U = (const float*)d_in[2];
    const float* Wa = (const float*)d_in[3];
    const float* ba = (const float*)d_in[4];
    const float* Wb = (const float*)d_in[5];
    const float* bb = (const float*)d_in[6];
    const float* Ws = (const float*)d_in[7];
    const float* bs = (const float*)d_in[8];
    const float* WS_ = (const float*)d_in[9];
    const float* bS = (const float*)d_in[10];
    const float* WM = (const float*)d_in[11];
    const float* bM = (const float*)d_in[12];
    const float* Ww = (const float*)d_in[13];
    const float* bw = (const float*)d_in[14];
    float* out = (float*)d_out;

    float *p_xt, *p_F, *p_Z, *p_Wcat, *p_cvec;
    cudaGetSymbolAddress((void**)&p_xt, g_xt);
    cudaGetSymbolAddress((void**)&p_F, g_F);
    cudaGetSymbolAddress((void**)&p_Z, g_Z);
    cudaGetSymbolAddress((void**)&p_Wcat, g_Wcat);
    cudaGetSymbolAddress((void**)&p_cvec, g_cvec);

    const size_t sU = (size_t)NN * NN;      // per-batch U stride
    const size_t sX = (size_t)NN * DD;      // per-batch [N,D] stride

    // coefficient / weight preprocessing
    partial_kernel<<<64, 128>>>(eigvs);
    coeff_kernel<<<2, 128>>>(Wa, ba, Wb, bb, Ws, bs);
    weight_kernel<<<769, 128>>>(WS_, WM, Ww, bS, bM, bw);

    // xt = U^T x   : TRANS_A
    gemm_n128<true, false><<<dim3(64, 2), 256>>>(U, x, p_xt, nullptr,
                                                 NN, NN, sU, sX, sX);
    // filter-bank features
    fbuild_kernel<<<512, 128>>>(eigvs);
    // Z = F @ Wcat  (flat M=8192, K=768)
    gemm_n128<false, false><<<dim3(128, 1), 256>>>(p_F, p_Wcat, p_Z, nullptr,
                                                   6 * DD, 6 * DD, 0, 0, 0);
    // out = U @ Z + cvec
    gemm_n128<false, true><<<dim3(64, 2), 256>>>(U, p_Z, out, p_cvec,
                                                 NN, NN, sU, sX, sX);
}

// round 2
// speedup vs baseline: 1.0003x; 1.0003x over previous
#include <cuda_runtime.h>
#include <cstddef>

typedef unsigned long long u64;

#define RHO 5
#define NJ 5
#define NN 4096
#define DD 128
#define NB 2

// ---- device scratch (allocation-free rule: __device__ globals) ----
__device__ float g_partial[NB * 32 * DD];
__device__ float g_acoef[NB * 8];
__device__ float g_bcoef[NB * 8];
__device__ float g_scale[NB * 8];
__device__ float g_Wcat[6 * DD * DD];     // [768][128] combined (WS@Ww, WM[j]@Ww)
__device__ float g_cvec[DD];              // combined bias
__device__ float g_xt[NB * NN * DD];      // U^T x
__device__ float g_F[(size_t)NB * NN * 6 * DD]; // filter-bank features [8192][768]
__device__ float g_Z[NB * NN * DD];       // F @ Wcat

// ---------------------------------------------------------------
// Stage 1: partial column sums of eigvs (for the pooled means)
// grid 64 (b*32+chunk), 128 threads
// ---------------------------------------------------------------
__global__ void partial_kernel(const float* __restrict__ eigvs) {
    int b = blockIdx.x >> 5, chunk = blockIdx.x & 31, d = threadIdx.x;
    const float* p = eigvs + ((size_t)b * NN + (size_t)chunk * 128) * DD + d;
    float s = 0.f;
#pragma unroll 8
    for (int r = 0; r < 128; r++) s += p[(size_t)r * DD];
    g_partial[(b * 32 + chunk) * DD + d] = s;
}

// ---------------------------------------------------------------
// Stage 2: reduce means -> Chebyshev coefficients a,b and scales
// grid 2 (batch), 128 threads
// ---------------------------------------------------------------
__global__ void coeff_kernel(const float* __restrict__ Wa, const float* __restrict__ ba,
                             const float* __restrict__ Wb, const float* __restrict__ bb,
                             const float* __restrict__ Ws, const float* __restrict__ bs) {
    __shared__ float mean[DD];
    int b = blockIdx.x, d = threadIdx.x;
    float s = 0.f;
    for (int c = 0; c < 32; c++) s += g_partial[(b * 32 + c) * DD + d];
    mean[d] = s * (1.0f / NN);
    __syncthreads();
    if (d < RHO) {
        float a = 0.f, bv = 0.f, sv = 0.f;
        for (int e = 0; e < DD; e++) {
            float m = mean[e];
            a += m * Wa[e * RHO + d];
            bv += m * Wb[e * RHO + d];
            sv += m * Ws[e * NJ + d];
        }
        g_acoef[b * 8 + d] = a + ba[d];
        g_bcoef[b * 8 + d] = bv + bb[d];
        sv += bs[d];
        g_scale[b * 8 + d] = 5.0f / (1.0f + expf(-sv));  // sigmoid * SCALE
    }
}

// ---------------------------------------------------------------
// Stage 3: fold channel matrices through Ww:
//   Wcat[s*128+i][d] = sum_e Wsrc_s[i][e] * Ww[e][d]
//   cvec[d] = (bS + sum_j bM[j]) @ Ww + bw
// grid 769, 128 threads
// ---------------------------------------------------------------
__global__ void weight_kernel(const float* __restrict__ WS_, const float* __restrict__ WM,
                              const float* __restrict__ Ww, const float* __restrict__ bS,
                              const float* __restrict__ bM, const float* __restrict__ bw) {
    int blk = blockIdx.x, d = threadIdx.x;
    if (blk < 6 * DD) {
        int s = blk >> 7, i = blk & 127;
        const float* wsrc = (s == 0) ? (WS_ + i * DD) : (WM + (size_t)(s - 1) * DD * DD + i * DD);
        float acc = 0.f;
        for (int e = 0; e < DD; e++) acc += wsrc[e] * Ww[e * DD + d];
        g_Wcat[blk * DD + d] = acc;
    } else {
        float acc = bw[d];
        for (int e = 0; e < DD; e++) {
            float cb = bS[e];
            for (int j = 0; j < NJ; j++) cb += bM[j * DD + e];
            acc += cb * Ww[e * DD + d];
        }
        g_cvec[d] = acc;
    }
}

// ---------------------------------------------------------------
// Stage 5: build filter-bank features
//   F[row][0*128+d]    = h(e) * xt
//   F[row][(1+j)*128+d]= g_j(scale_j*e) * xt
// grid 512 (16 rows each), 128 threads
// ---------------------------------------------------------------
__global__ void fbuild_kernel(const float* __restrict__ eigvs) {
    int row0 = blockIdx.x * 16;
    int d = threadIdx.x;
    for (int r = 0; r < 16; r++) {
        int row = row0 + r;
        int b = row >> 12;
        const float* ac = g_acoef + b * 8;
        const float* bc = g_bcoef + b * 8;
        const float* sc = g_scale + b * 8;
        float e = eigvs[(size_t)row * DD + d];
        float xv = g_xt[(size_t)row * DD + d];
        // h = sum_i b_i T_{2i}(e)  (reference recurrence exactly)
        float To = 1.f, Te = e, h = bc[0];
#pragma unroll
        for (int i = 1; i < RHO; i++) {
            To = 2.f * e * Te - To;
            Te = 2.f * e * To - Te;
            h += bc[i] * To;
        }
        float* Fr = g_F + (size_t)row * (6 * DD);
        Fr[d] = h * xv;
#pragma unroll
        for (int j = 0; j < NJ; j++) {
            float sx = sc[j] * e;
            float To2 = 1.f, Te2 = sx, g = ac[0] * Te2;
#pragma unroll
            for (int i = 1; i < RHO; i++) {
                To2 = 2.f * sx * Te2 - To2;
                Te2 = 2.f * sx * To2 - Te2;
                g += ac[i] * Te2;
            }
            Fr[(1 + j) * DD + d] = g * xv;
        }
    }
}

// ---------------------------------------------------------------
// GEMM: C[M,128] = op(A) @ B[K,128] (+bias).  BM=64, BN=128, BK=32.
// 256 threads, each thread: 4 rows x 8 cols as 4x4 f32x2 accumulators.
// Register-prefetched single smem buffer. Uses packed fma.rn.f32x2
// (FFMA2) for 2x fp32 FMA throughput on sm_103a.
// TRANS_A: A element (k, row) at A[k*lda + row]   (U^T x case)
// else:    A element (row, k) at A[row*lda + k]
// ---------------------------------------------------------------
template <bool TRANS_A, bool ADD_BIAS>
__global__ void __launch_bounds__(256)
gemm_n128(const float* __restrict__ A, const float* __restrict__ B,
          float* __restrict__ C, const float* __restrict__ bias,
          int K, int lda, size_t strideA, size_t strideB, size_t strideC) {
    __shared__ float As[32][65];
    __shared__ __align__(16) float Bs[32][128];

    const int tid = threadIdx.x;
    const int m0 = blockIdx.x * 64;
    const int bb = blockIdx.y;
    A += (size_t)bb * strideA;
    B += (size_t)bb * strideB;
    C += (size_t)bb * strideC;

    const int rbase = (tid >> 4) << 2;  // 0..60
    const int cbase = (tid & 15) << 3;  // 0..120

    u64 acc[4][4];
#pragma unroll
    for (int i = 0; i < 4; i++)
#pragma unroll
        for (int j = 0; j < 4; j++) acc[i][j] = 0ULL;

    // per-thread load coordinates
    const int kk0A = TRANS_A ? (tid >> 6) : (tid & 31);
    const int mmA = TRANS_A ? (tid & 63) : (tid >> 5);
    const int kkB = tid >> 5;
    const int c4 = (tid & 31) * 4;

    float aR[8];
    float4 bR[4];
    // prologue: load tile k0=0 into registers
#pragma unroll
    for (int i = 0; i < 8; i++) {
        if (TRANS_A)
            aR[i] = A[(size_t)(kk0A + 4 * i) * lda + m0 + mmA];
        else
            aR[i] = A[(size_t)(m0 + mmA + 8 * i) * lda + kk0A];
    }
#pragma unroll
    for (int i = 0; i < 4; i++)
        bR[i] = *(const float4*)&B[(size_t)(kkB + 8 * i) * 128 + c4];

    for (int k0 = 0; k0 < K; k0 += 32) {
        // stage registers -> smem
#pragma unroll
        for (int i = 0; i < 8; i++) {
            if (TRANS_A)
                As[kk0A + 4 * i][mmA] = aR[i];
            else
                As[kk0A][mmA + 8 * i] = aR[i];
        }
#pragma unroll
        for (int i = 0; i < 4; i++)
            *(float4*)&Bs[kkB + 8 * i][c4] = bR[i];
        __syncthreads();

        // prefetch next tile to registers (in flight during compute)
        const int kn = k0 + 32;
        if (kn < K) {
#pragma unroll
            for (int i = 0; i < 8; i++) {
                if (TRANS_A)
                    aR[i] = A[(size_t)(kn + kk0A + 4 * i) * lda + m0 + mmA];
                else
                    aR[i] = A[(size_t)(m0 + mmA + 8 * i) * lda + kn + kk0A];
            }
#pragma unroll
            for (int i = 0; i < 4; i++)
                bR[i] = *(const float4*)&B[(size_t)(kn + kkB + 8 * i) * 128 + c4];
        }

        // compute 32 k-steps with packed f32x2 FMAs
#pragma unroll
        for (int kk = 0; kk < 32; kk++) {
            u64 ap[4];
#pragma unroll
            for (int i = 0; i < 4; i++) {
                float av = As[kk][rbase + i];
                asm("mov.b64 %0, {%1, %1};" : "=l"(ap[i]) : "f"(av));
            }
            const ulonglong2* bq = (const ulonglong2*)&Bs[kk][cbase];
            ulonglong2 q0 = bq[0], q1 = bq[1];
            u64 bp[4] = {q0.x, q0.y, q1.x, q1.y};
#pragma unroll
            for (int i = 0; i < 4; i++)
#pragma unroll
                for (int j = 0; j < 4; j++)
                    asm("fma.rn.f32x2 %0, %1, %2, %0;"
                        : "+l"(acc[i][j])
                        : "l"(ap[i]), "l"(bp[j]));
        }
        __syncthreads();
    }

    // epilogue
#pragma unroll
    for (int i = 0; i < 4; i++) {
        float out[8];
#pragma unroll
        for (int j = 0; j < 4; j++) {
            float lo, hi;
            asm("mov.b64 {%0, %1}, %2;" : "=f"(lo), "=f"(hi) : "l"(acc[i][j]));
            out[2 * j] = lo;
            out[2 * j + 1] = hi;
        }
        if (ADD_BIAS) {
#pragma unroll
            for (int j = 0; j < 8; j++) out[j] += bias[cbase + j];
        }
        float4* dst = (float4*)&C[(size_t)(m0 + rbase + i) * 128 + cbase];
        dst[0] = make_float4(out[0], out[1], out[2], out[3]);
        dst[1] = make_float4(out[4], out[5], out[6], out[7]);
    }
}

// ---------------------------------------------------------------
extern "C" void kernel_launch(void* const* d_in, const int* in_sizes, int n_in,
                              void* d_out, int out_size) {
    const float* eigvs = (const float*)d_in[0];
    const float* x = (const float*)d_in[1];
    const float* U = (const float*)d_in[2];
    const float* Wa = (const float*)d_in[3];
    const float* ba = (const float*)d_in[4];
    const float* Wb = (const float*)d_in[5];
    const float* bb = (const float*)d_in[6];
    const float* Ws = (const float*)d_in[7];
    const float* bs = (const float*)d_in[8];
    const float* WS_ = (const float*)d_in[9];
    const float* bS = (const float*)d_in[10];
    const float* WM = (const float*)d_in[11];
    const float* bM = (const float*)d_in[12];
    const float* Ww = (const float*)d_in[13];
    const float* bw = (const float*)d_in[14];
    float* out = (float*)d_out;

    float *p_xt, *p_F, *p_Z, *p_Wcat, *p_cvec;
    cudaGetSymbolAddress((void**)&p_xt, g_xt);
    cudaGetSymbolAddress((void**)&p_F, g_F);
    cudaGetSymbolAddress((void**)&p_Z, g_Z);
    cudaGetSymbolAddress((void**)&p_Wcat, g_Wcat);
    cudaGetSymbolAddress((void**)&p_cvec, g_cvec);

    const size_t sU = (size_t)NN * NN;      // per-batch U stride
    const size_t sX = (size_t)NN * DD;      // per-batch [N,D] stride

    // coefficient / weight preprocessing
    partial_kernel<<<64, 128>>>(eigvs);
    coeff_kernel<<<2, 128>>>(Wa, ba, Wb, bb, Ws, bs);
    weight_kernel<<<769, 128>>>(WS_, WM, Ww, bS, bM, bw);

    // xt = U^T x   : TRANS_A
    gemm_n128<true, false><<<dim3(64, 2), 256>>>(U, x, p_xt, nullptr,
                                                 NN, NN, sU, sX, sX);
    // filter-bank features
    fbuild_kernel<<<512, 128>>>(eigvs);
    // Z = F @ Wcat  (flat M=8192, K=768)
    gemm_n128<false, false><<<dim3(128, 1), 256>>>(p_F, p_Wcat, p_Z, nullptr,
                                                   6 * DD, 6 * DD, 0, 0, 0);
    // out = U @ Z + cvec
    gemm_n128<false, true><<<dim3(64, 2), 256>>>(U, p_Z, out, p_cvec,
                                                 NN, NN, sU, sX, sX);
}

// round 4
// speedup vs baseline: 3.2108x; 3.2098x over previous
#include <cuda_runtime.h>
#include <cuda_bf16.h>
#include <cstdint>
#include <cstddef>

typedef __nv_bfloat16 bf16;
typedef unsigned int u32;

#define NN 4096
#define DD 128
#define NB 2
#define RHO 5
#define NJ 5
#define KC 64
#define STAGE_B 49152          // A(hi+lo) 32KB + B(hi+lo) 16KB
#define SMEM_TOTAL (3 * STAGE_B)

// ---------------- device scratch ----------------
__device__ bf16 g_U_hi[(size_t)NB * NN * NN];
__device__ bf16 g_U_lo[(size_t)NB * NN * NN];
__device__ bf16 g_x_hi[(size_t)NB * NN * DD];
__device__ bf16 g_x_lo[(size_t)NB * NN * DD];
__device__ bf16 g_Z_hi[(size_t)NB * NN * DD];
__device__ bf16 g_Z_lo[(size_t)NB * NN * DD];
__device__ float g_xt[(size_t)NB * NN * DD];
__device__ bf16 g_F_hi[(size_t)NB * NN * 6 * DD];
__device__ bf16 g_F_lo[(size_t)NB * NN * 6 * DD];
__device__ bf16 g_Wc_hi[6 * DD * DD];   // [768 k][128 d]
__device__ bf16 g_Wc_lo[6 * DD * DD];
__device__ float g_partial[NB * 32 * DD];
__device__ float g_acoef[NB * 8];
__device__ float g_bcoef[NB * 8];
__device__ float g_scale[NB * 8];
__device__ float g_cvec[DD];

// ---------------- helpers ----------------
__device__ __forceinline__ u32 smem_u32(const void* p) {
    u32 a;
    asm("{ .reg .u64 t; cvta.to.shared.u64 t, %1; cvt.u32.u64 %0, t; }" : "=r"(a) : "l"(p));
    return a;
}
__device__ __forceinline__ void split2(float v, bf16& h, bf16& l) {
    h = __float2bfloat16_rn(v);
    l = __float2bfloat16_rn(v - __bfloat162float(h));
}
__device__ __forceinline__ void ldsm4(u32 a, u32* r) {
    asm volatile("ldmatrix.sync.aligned.m8n8.x4.shared.b16 {%0,%1,%2,%3}, [%4];"
                 : "=r"(r[0]), "=r"(r[1]), "=r"(r[2]), "=r"(r[3]) : "r"(a));
}
__device__ __forceinline__ void ldsm4t(u32 a, u32* r) {
    asm volatile("ldmatrix.sync.aligned.m8n8.x4.trans.shared.b16 {%0,%1,%2,%3}, [%4];"
                 : "=r"(r[0]), "=r"(r[1]), "=r"(r[2]), "=r"(r[3]) : "r"(a));
}
__device__ __forceinline__ void mma16816(float* c, const u32* a, const u32* b) {
    asm volatile(
        "mma.sync.aligned.m16n8k16.row.col.f32.bf16.bf16.f32 "
        "{%0,%1,%2,%3}, {%4,%5,%6,%7}, {%8,%9}, {%0,%1,%2,%3};"
        : "+f"(c[0]), "+f"(c[1]), "+f"(c[2]), "+f"(c[3])
        : "r"(a[0]), "r"(a[1]), "r"(a[2]), "r"(a[3]), "r"(b[0]), "r"(b[1]));
}

// ---------------- elementwise fp32 -> bf16 hi/lo ----------------
__global__ void convert_split_kernel(const float* __restrict__ src, bf16* __restrict__ oh,
                                     bf16* __restrict__ ol) {
    size_t idx = (size_t)blockIdx.x * blockDim.x + threadIdx.x;
    float4 v = ((const float4*)src)[idx];
    bf16 h0, l0, h1, l1, h2, l2, h3, l3;
    split2(v.x, h0, l0); split2(v.y, h1, l1);
    split2(v.z, h2, l2); split2(v.w, h3, l3);
    ((__nv_bfloat162*)oh)[idx * 2] = __nv_bfloat162(h0, h1);
    ((__nv_bfloat162*)oh)[idx * 2 + 1] = __nv_bfloat162(h2, h3);
    ((__nv_bfloat162*)ol)[idx * 2] = __nv_bfloat162(l0, l1);
    ((__nv_bfloat162*)ol)[idx * 2 + 1] = __nv_bfloat162(l2, l3);
}

// ---------------- coefficient path (validated R1) ----------------
__global__ void partial_kernel(const float* __restrict__ eigvs) {
    int b = blockIdx.x >> 5, chunk = blockIdx.x & 31, d = threadIdx.x;
    const float* p = eigvs + ((size_t)b * NN + (size_t)chunk * 128) * DD + d;
    float s = 0.f;
#pragma unroll 8
    for (int r = 0; r < 128; r++) s += p[(size_t)r * DD];
    g_partial[(b * 32 + chunk) * DD + d] = s;
}

__global__ void coeff_kernel(const float* __restrict__ Wa, const float* __restrict__ ba,
                             const float* __restrict__ Wb, const float* __restrict__ bb,
                             const float* __restrict__ Ws, const float* __restrict__ bs) {
    __shared__ float mean[DD];
    int b = blockIdx.x, d = threadIdx.x;
    float s = 0.f;
    for (int c = 0; c < 32; c++) s += g_partial[(b * 32 + c) * DD + d];
    mean[d] = s * (1.0f / NN);
    __syncthreads();
    if (d < RHO) {
        float a = 0.f, bv = 0.f, sv = 0.f;
        for (int e = 0; e < DD; e++) {
            float m = mean[e];
            a += m * Wa[e * RHO + d];
            bv += m * Wb[e * RHO + d];
            sv += m * Ws[e * NJ + d];
        }
        g_acoef[b * 8 + d] = a + ba[d];
        g_bcoef[b * 8 + d] = bv + bb[d];
        sv += bs[d];
        g_scale[b * 8 + d] = 5.0f / (1.0f + expf(-sv));
    }
}

__global__ void weight_kernel(const float* __restrict__ WS_, const float* __restrict__ WM,
                              const float* __restrict__ Ww, const float* __restrict__ bS,
                              const float* __restrict__ bM, const float* __restrict__ bw) {
    int blk = blockIdx.x, d = threadIdx.x;
    if (blk < 6 * DD) {
        int s = blk >> 7, i = blk & 127;
        const float* wsrc = (s == 0) ? (WS_ + i * DD) : (WM + (size_t)(s - 1) * DD * DD + i * DD);
        float acc = 0.f;
        for (int e = 0; e < DD; e++) acc += wsrc[e] * Ww[e * DD + d];
        bf16 h, l; split2(acc, h, l);
        g_Wc_hi[(size_t)blk * DD + d] = h;
        g_Wc_lo[(size_t)blk * DD + d] = l;
    } else {
        float acc = bw[d];
        for (int e = 0; e < DD; e++) {
            float cb = bS[e];
            for (int j = 0; j < NJ; j++) cb += bM[j * DD + e];
            acc += cb * Ww[e * DD + d];
        }
        g_cvec[d] = acc;
    }
}

__global__ void fbuild_kernel(const float* __restrict__ eigvs) {
    int row0 = blockIdx.x * 16, d = threadIdx.x;
    for (int r = 0; r < 16; r++) {
        int row = row0 + r, b = row >> 12;
        const float* ac = g_acoef + b * 8;
        const float* bc = g_bcoef + b * 8;
        const float* sc = g_scale + b * 8;
        float e = eigvs[(size_t)row * DD + d];
        float xv = g_xt[(size_t)row * DD + d];
        float To = 1.f, Te = e, h = bc[0];
#pragma unroll
        for (int i = 1; i < RHO; i++) {
            To = 2.f * e * Te - To;
            Te = 2.f * e * To - Te;
            h += bc[i] * To;
        }
        size_t fb = (size_t)row * (6 * DD);
        bf16 hh, hl; split2(h * xv, hh, hl);
        g_F_hi[fb + d] = hh; g_F_lo[fb + d] = hl;
#pragma unroll
        for (int j = 0; j < NJ; j++) {
            float sx = sc[j] * e;
            float To2 = 1.f, Te2 = sx, g = ac[0] * Te2;
#pragma unroll
            for (int i = 1; i < RHO; i++) {
                To2 = 2.f * sx * Te2 - To2;
                Te2 = 2.f * sx * To2 - Te2;
                g += ac[i] * Te2;
            }
            bf16 gh, gl; split2(g * xv, gh, gl);
            g_F_hi[fb + (1 + j) * DD + d] = gh;
            g_F_lo[fb + (1 + j) * DD + d] = gl;
        }
    }
}

// ---------------- mma.sync GEMM ----------------
// C[M,128] tiles: per CTA BM=128 (blockIdx.x), BN=64 (blockIdx.y half), K chunks of 64.
// A: TRANSA ? A[k][m] (m-contig, tile rows=k, 256B)  : A[m][k] (k-contig, tile rows=m, 128B)
// B: B[k][n] n-contig (ldmatrix.trans)
template <bool TRANSA>
__device__ __forceinline__ void issue_loads(u32 sb, int st, int k0,
                                            const bf16* Ah, const bf16* Al,
                                            const bf16* Bh, const bf16* Bl,
                                            int lda, int ldb, int tid) {
    u32 Abase = sb + st * STAGE_B;
    u32 Bbase = Abase + 32768;
#pragma unroll
    for (int half = 0; half < 2; half++) {
        const bf16* src = half ? Al : Ah;
        u32 ab = Abase + half * 16384;
#pragma unroll
        for (int i = 0; i < 4; i++) {
            int q = tid + i * 256;
            u32 dst; const char* g;
            if (TRANSA) {
                int kr = q >> 4, ch = q & 15;
                g = (const char*)(src + (size_t)(k0 + kr) * lda) + ch * 16;
                dst = ab + kr * 256 + ((ch ^ (kr & 7)) * 16);
            } else {
                int m = q >> 3, ch = q & 7;
                g = (const char*)(src + (size_t)m * lda + k0) + ch * 16;
                dst = ab + m * 128 + ((ch ^ (m & 7)) * 16);
            }
            asm volatile("cp.async.cg.shared.global [%0], [%1], 16;" :: "r"(dst), "l"(g));
        }
    }
#pragma unroll
    for (int half = 0; half < 2; half++) {
        const bf16* src = half ? Bl : Bh;
        u32 bb = Bbase + half * 8192;
#pragma unroll
        for (int i = 0; i < 2; i++) {
            int q = tid + i * 256;
            int kr = q >> 3, ch = q & 7;
            const char* g = (const char*)(src + (size_t)(k0 + kr) * ldb) + ch * 16;
            u32 dst = bb + kr * 128 + ((ch ^ (kr & 7)) * 16);
            asm volatile("cp.async.cg.shared.global [%0], [%1], 16;" :: "r"(dst), "l"(g));
        }
    }
    asm volatile("cp.async.commit_group;" ::: "memory");
}

// OUTMODE: 0 = fp32, 1 = fp32+bias, 2 = bf16 hi/lo split
template <bool TRANSA, int OUTMODE>
__global__ void __launch_bounds__(256)
mma_gemm(const bf16* __restrict__ Ah, const bf16* __restrict__ Al,
         const bf16* __restrict__ Bh, const bf16* __restrict__ Bl,
         float* __restrict__ C, bf16* __restrict__ Zh, bf16* __restrict__ Zl,
         const float* __restrict__ bias,
         int K, int lda, int ldb, size_t aB, size_t bB, size_t cB) {
    extern __shared__ char smem[];
    u32 sb = smem_u32(smem);
    int tid = threadIdx.x, lane = tid & 31, wid = tid >> 5;
    int wm = wid & 3, wn = wid >> 2;
    int bx = blockIdx.x, nh = blockIdx.y, bz = blockIdx.z;

    if (TRANSA) { Ah += bz * aB + (size_t)bx * 128; Al += bz * aB + (size_t)bx * 128; }
    else        { Ah += bz * aB + (size_t)bx * 128 * lda; Al += bz * aB + (size_t)bx * 128 * lda; }
    Bh += bz * bB + (size_t)nh * 64;
    Bl += bz * bB + (size_t)nh * 64;

    float acc[2][4][4];
#pragma unroll
    for (int a = 0; a < 2; a++)
#pragma unroll
        for (int b = 0; b < 4; b++)
#pragma unroll
            for (int c = 0; c < 4; c++) acc[a][b][c] = 0.f;

    const int NCH = K / KC;
    issue_loads<TRANSA>(sb, 0, 0, Ah, Al, Bh, Bl, lda, ldb, tid);
    issue_loads<TRANSA>(sb, 1, KC, Ah, Al, Bh, Bl, lda, ldb, tid);
    issue_loads<TRANSA>(sb, 2, 2 * KC, Ah, Al, Bh, Bl, lda, ldb, tid);

    for (int c = 0; c < NCH; c++) {
        int st = c % 3;
        int rem = NCH - 1 - c;
        if (rem >= 2) asm volatile("cp.async.wait_group 2;" ::: "memory");
        else if (rem == 1) asm volatile("cp.async.wait_group 1;" ::: "memory");
        else asm volatile("cp.async.wait_group 0;" ::: "memory");
        __syncthreads();

        u32 Ab = sb + st * STAGE_B;
        u32 Bb = Ab + 32768;
#pragma unroll
        for (int s = 0; s < 4; s++) {
            u32 ah[2][4], al[2][4], bh[2][4], bl[2][4];
#pragma unroll
            for (int mt = 0; mt < 2; mt++) {
                u32 off;
                if (TRANSA) {
                    int kr = 16 * s + (lane & 7) + ((lane >> 4) << 3);
                    int mch = wm * 4 + mt * 2 + ((lane >> 3) & 1);
                    off = kr * 256 + ((mch ^ (kr & 7)) << 4);
                    ldsm4t(Ab + off, ah[mt]);
                    ldsm4t(Ab + 16384 + off, al[mt]);
                } else {
                    int row = wm * 32 + mt * 16 + (lane & 15);
                    int ch = 2 * s + (lane >> 4);
                    off = row * 128 + ((ch ^ (row & 7)) << 4);
                    ldsm4(Ab + off, ah[mt]);
                    ldsm4(Ab + 16384 + off, al[mt]);
                }
            }
#pragma unroll
            for (int nt = 0; nt < 2; nt++) {
                int kr = 16 * s + (lane & 7) + ((lane >> 3) & 1) * 8;
                int nch = wn * 4 + nt * 2 + (lane >> 4);
                u32 off = kr * 128 + ((nch ^ (kr & 7)) << 4);
                ldsm4t(Bb + off, bh[nt]);
                ldsm4t(Bb + 8192 + off, bl[nt]);
            }
#pragma unroll
            for (int mt = 0; mt < 2; mt++)
#pragma unroll
                for (int nt = 0; nt < 2; nt++)
#pragma unroll
                    for (int oc = 0; oc < 2; oc++) {
                        float* cc = acc[mt][nt * 2 + oc];
                        mma16816(cc, ah[mt], &bh[nt][oc * 2]);
                        mma16816(cc, ah[mt], &bl[nt][oc * 2]);
                        mma16816(cc, al[mt], &bh[nt][oc * 2]);
                    }
        }
        __syncthreads();
        if (c + 3 < NCH)
            issue_loads<TRANSA>(sb, st, (c + 3) * KC, Ah, Al, Bh, Bl, lda, ldb, tid);
    }

    // epilogue
#pragma unroll
    for (int mt = 0; mt < 2; mt++)
#pragma unroll
        for (int j = 0; j < 4; j++) {
            int mloc = bx * 128 + wm * 32 + mt * 16 + (lane >> 2);
            int col = nh * 64 + wn * 32 + j * 8 + (lane & 3) * 2;
#pragma unroll
            for (int rr = 0; rr < 2; rr++) {
                float v0 = acc[mt][j][rr * 2], v1 = acc[mt][j][rr * 2 + 1];
                size_t off = (size_t)(mloc + rr * 8) * 128 + col;
                if (OUTMODE == 2) {
                    bf16 h0, l0, h1, l1;
                    split2(v0, h0, l0); split2(v1, h1, l1);
                    *(__nv_bfloat162*)(Zh + bz * cB + off) = __nv_bfloat162(h0, h1);
                    *(__nv_bfloat162*)(Zl + bz * cB + off) = __nv_bfloat162(l0, l1);
                } else {
                    if (OUTMODE == 1) { v0 += bias[col]; v1 += bias[col + 1]; }
                    *(float2*)(C + bz * cB + off) = make_float2(v0, v1);
                }
            }
        }
}

// ---------------------------------------------------------------
extern "C" void kernel_launch(void* const* d_in, const int* in_sizes, int n_in,
                              void* d_out, int out_size) {
    const float* eigvs = (const float*)d_in[0];
    const float* x = (const float*)d_in[1];
    const float* U = (const float*)d_in[2];
    const float* Wa = (const float*)d_in[3];
    const float* ba = (const float*)d_in[4];
    const float* Wb = (const float*)d_in[5];
    const float* bb = (const float*)d_in[6];
    const float* Ws = (const float*)d_in[7];
    const float* bs = (const float*)d_in[8];
    const float* WS_ = (const float*)d_in[9];
    const float* bS = (const float*)d_in[10];
    const float* WM = (const float*)d_in[11];
    const float* bM = (const float*)d_in[12];
    const float* Ww = (const float*)d_in[13];
    const float* bw = (const float*)d_in[14];
    float* out = (float*)d_out;

    cudaFuncSetAttribute(mma_gemm<true, 0>, cudaFuncAttributeMaxDynamicSharedMemorySize, SMEM_TOTAL);
    cudaFuncSetAttribute(mma_gemm<false, 1>, cudaFuncAttributeMaxDynamicSharedMemorySize, SMEM_TOTAL);
    cudaFuncSetAttribute(mma_gemm<false, 2>, cudaFuncAttributeMaxDynamicSharedMemorySize, SMEM_TOTAL);

    bf16 *pUh, *pUl, *pxh, *pxl, *pZh, *pZl, *pFh, *pFl, *pWh, *pWl;
    float *pxt, *pcv;
    cudaGetSymbolAddress((void**)&pUh, g_U_hi);
    cudaGetSymbolAddress((void**)&pUl, g_U_lo);
    cudaGetSymbolAddress((void**)&pxh, g_x_hi);
    cudaGetSymbolAddress((void**)&pxl, g_x_lo);
    cudaGetSymbolAddress((void**)&pZh, g_Z_hi);
    cudaGetSymbolAddress((void**)&pZl, g_Z_lo);
    cudaGetSymbolAddress((void**)&pFh, g_F_hi);
    cudaGetSymbolAddress((void**)&pFl, g_F_lo);
    cudaGetSymbolAddress((void**)&pWh, g_Wc_hi);
    cudaGetSymbolAddress((void**)&pWl, g_Wc_lo);
    cudaGetSymbolAddress((void**)&pxt, g_xt);
    cudaGetSymbolAddress((void**)&pcv, g_cvec);

    const size_t sU = (size_t)NN * NN;
    const size_t sX = (size_t)NN * DD;

    partial_kernel<<<64, 128>>>(eigvs);
    coeff_kernel<<<2, 128>>>(Wa, ba, Wb, bb, Ws, bs);
    weight_kernel<<<769, 128>>>(WS_, WM, Ww, bS, bM, bw);
    convert_split_kernel<<<32768, 256>>>(U, pUh, pUl);
    convert_split_kernel<<<1024, 256>>>(x, pxh, pxl);

    // xt = U^T x : A = U^T via TRANSA tiles of U[k=urow][m=ucol], B = x[k][d]
    mma_gemm<true, 0><<<dim3(32, 2, 2), 256, SMEM_TOTAL>>>(
        pUh, pUl, pxh, pxl, pxt, nullptr, nullptr, nullptr,
        NN, NN, DD, sU, sX, sX);

    fbuild_kernel<<<512, 128>>>(eigvs);

    // Z = F @ Wc : A = F[8192][768], B = Wc[768][128]; output split bf16
    mma_gemm<false, 2><<<dim3(64, 2, 1), 256, SMEM_TOTAL>>>(
        pFh, pFl, pWh, pWl, nullptr, pZh, pZl, nullptr,
        6 * DD, 6 * DD, DD, 0, 0, 0);

    // out = U @ Z + cvec : A = U[m][k=ucol], B = Z[k][d]
    mma_gemm<false, 1><<<dim3(32, 2, 2), 256, SMEM_TOTAL>>>(
        pUh, pUl, pZh, pZl, out, nullptr, nullptr, pcv,
        NN, NN, DD, sU, sX, sX);
}